// round 9
// baseline (speedup 1.0000x reference)
#include <cuda_runtime.h>

#define T_STEPS 512
#define BATCH   256
#define INDIM   8
#define HID     512
#define OUTD    5
#define NCTA    128
#define THREADS 256
#define WST     528            // weight row stride; LDS.128 conflict-free (4*gid+q distinct)
#define XST0    52             // 6-tile exchange stride: gid*52%32 all-distinct
#define XST2    28             // 3-tile exchange stride: gid*28%32 all-distinct
#define NPHASE  (T_STEPS + 1)

__device__ float    g_h0[2][BATCH * HID];
__device__ float    g_h1[2][BATCH * HID];
__device__ unsigned g_bar[NPHASE];

// hidden element (k,row) at ((k&3)*32 + (k>>4))*1024 + row*4 + ((k>>2)&3)
__device__ __forceinline__ int hoff(int k, int row) {
    return (((k & 3) * 32 + (k >> 4)) << 10) + (row << 2) + ((k >> 2) & 3);
}
// weight in-16-block K permutation: pos = (k&3)*4 + ((k>>2)&3)
__device__ __forceinline__ int wp16(int k) {
    return (k & ~15) + ((k & 3) << 2) + ((k >> 2) & 3);
}
__device__ __forceinline__ float to_tf32(float x) {
    float r; asm("cvt.rna.tf32.f32 %0, %1;" : "=f"(r) : "f"(x)); return r;
}
__device__ __forceinline__ float sig_(float x) { return 1.f / (1.f + __expf(-x)); }
__device__ __forceinline__ float tanh_(float x) {
    float e = __expf(2.f * x); return 1.f - 2.f / (e + 1.f);
}
__device__ __forceinline__ void mma_tf32(float* c, const unsigned* a, float bx, float by) {
    asm volatile(
        "mma.sync.aligned.m16n8k8.row.col.f32.tf32.tf32.f32 "
        "{%0,%1,%2,%3}, {%4,%5,%6,%7}, {%8,%9}, {%0,%1,%2,%3};\n"
        : "+f"(c[0]), "+f"(c[1]), "+f"(c[2]), "+f"(c[3])
        : "r"(a[0]), "r"(a[1]), "r"(a[2]), "r"(a[3]),
          "r"(__float_as_uint(bx)), "r"(__float_as_uint(by)));
}

__device__ __forceinline__ void grid_barrier(int p) {
    __syncthreads();
    if (threadIdx.x == 0) {
        unsigned* c = &g_bar[p];
        asm volatile("red.release.gpu.global.add.u32 [%0], %1;" :: "l"(c), "r"(1u) : "memory");
        unsigned v;
        do {
            asm volatile("ld.acquire.gpu.global.u32 %0, [%1];" : "=r"(v) : "l"(c) : "memory");
        } while (v < NCTA);
    }
    __syncthreads();
}

__global__ void reset_kernel() {
    int tid = blockIdx.x * blockDim.x + threadIdx.x;
    int stride = gridDim.x * blockDim.x;
    for (int i = tid; i < BATCH * HID; i += stride) { g_h0[1][i] = 0.f; g_h1[1][i] = 0.f; }
    if (tid < NPHASE) g_bar[tid] = 0u;
}

extern __shared__ float smem[];

// 128 CTAs: ms = cta&1 (128-row half), U = (cta>>1)*8 (8 hidden units).
// 8 warps, each owning 4 m16-tiles (64 rows) so one B LDS.128 feeds 8 MMAs:
//   grp0 (w0-3) = mg(2: 64 rows) x ks(2: K half): sides 0+1 (tiles 0..5, A=h0[p-1])
//   grp1 (w4-7) = mg(2) x ks(2): side 2 (tiles 6..8, A=h1[p-2])
// Tile column c maps to unit (c>>1)+((c&1)<<2) so each thread owns units {q,q+4},
// which are ADJACENT words in hoff layout -> STG.64 stores, and h-prev for the
// z-blend is carried in registers across phases (no reload).
__global__ void __launch_bounds__(THREADS, 1) gru_persistent(
    const float* __restrict__ x,
    const float* __restrict__ Wih0, const float* __restrict__ Whh0,
    const float* __restrict__ bih0, const float* __restrict__ bhh0,
    const float* __restrict__ Wih1, const float* __restrict__ Whh1,
    const float* __restrict__ bih1, const float* __restrict__ bhh1,
    const float* __restrict__ Wout, const float* __restrict__ bout,
    float* __restrict__ out)
{
    float* Wsm = smem;                       // 72 x WST
    float* xsm = smem + 72 * WST;            // 128 x 8
    float* wih = xsm + 1024;                 // 24 x 8
    float* b0i = wih + 192;  float* b0h = b0i + 24;
    float* b1i = b0h + 24;   float* b1h = b1i + 24;
    float* xch0 = b1h + 24;                  // 128 x XST0 (grp0-ks1: tiles 0..5)
    float* xch1 = xch0 + 128 * XST0;         // 128 x XST2 (grp0-ks0: tiles 3..5)
    float* xch2 = xch1 + 128 * XST2;         // 128 x XST2 (grp1-ks1: tiles 6..8)

    const int tid  = threadIdx.x;
    const int cta  = blockIdx.x;
    const int lane = tid & 31;
    const int warp = tid >> 5;
    const int gid  = lane >> 2;
    const int q    = lane & 3;
    const bool g1  = (warp >= 4);
    const int mg   = warp & 1;               // 64-row group
    const int ks   = (warp >> 1) & 1;        // K half
    const int ms   = cta & 1;
    const int U    = (cta >> 1) * 8;

    // ---- stage weights once (with column->unit remap) ----
    for (int i = tid; i < 72 * HID; i += THREADS) {
        int j = i >> 9, k = i & (HID - 1);
        int tile = j >> 3, c = j & 7;
        int side = tile / 3, gate = tile % 3;
        int u = (c >> 1) + ((c & 1) << 2);
        const float* W = (side == 0) ? Whh0 : (side == 1) ? Wih1 : Whh1;
        Wsm[j * WST + wp16(k)] = to_tf32(W[(gate * HID + U + u) * HID + k]);
    }
    for (int i = tid; i < 24 * INDIM; i += THREADS) {
        int j = i >> 3, kk = i & 7;
        wih[i] = Wih0[((j >> 3) * HID + U + (j & 7)) * INDIM + kk];
    }
    if (tid < 24) {
        int g3 = tid >> 3, u = tid & 7;
        b0i[tid] = bih0[g3 * HID + U + u]; b0h[tid] = bhh0[g3 * HID + U + u];
        b1i[tid] = bih1[g3 * HID + U + u]; b1h[tid] = bhh1[g3 * HID + U + u];
    }
    __syncthreads();

    // carried h-prev (rounded), per epilogue thread: [mt][hh][e]
    float hc[4][2][2];
    #pragma unroll
    for (int mt = 0; mt < 4; ++mt)
        #pragma unroll
        for (int hh = 0; hh < 2; ++hh) { hc[mt][hh][0] = 0.f; hc[mt][hh][1] = 0.f; }

    for (int p = 0; p < NPHASE; ++p) {
        const float* A0 = g_h0[(p + 1) & 1];     // h0[p-1]
        const float* A1 = g_h1[p & 1];           // h1[p-2]
        float* H0n = g_h0[p & 1];                // h0[p]
        float* H1n = g_h1[(p + 1) & 1];          // h1[p-1]

        {   // stage x_t slice (all 256 threads, one float4 each)
            int pp = (p < T_STEPS) ? p : (T_STEPS - 1);
            ((float4*)xsm)[tid] =
                ((const float4*)(x + ((size_t)pp * BATCH + ms * 128) * INDIM))[tid];
        }

        const int r0 = ms * 128 + mg * 64 + gid;

        float acc[6][4][4];                      // [tile][mtile][cr]
        #pragma unroll
        for (int j = 0; j < 6; ++j)
            #pragma unroll
            for (int mt = 0; mt < 4; ++mt)
                #pragma unroll
                for (int e = 0; e < 4; ++e) acc[j][mt][e] = 0.f;

        if (!g1) {
            // ---------- grp0: sides 0+1 (A = h0[p-1]), K half, 4 m-tiles ----------
            #pragma unroll 2
            for (int tt = 0; tt < 16; ++tt) {
                const int t = ks * 16 + tt;
                const float* ab = A0 + ((q * 32 + t) << 10);
                float4 v[4][2];
                #pragma unroll
                for (int mt = 0; mt < 4; ++mt)
                    #pragma unroll
                    for (int rg = 0; rg < 2; ++rg)
                        v[mt][rg] = __ldcg((const float4*)(ab + ((r0 + mt * 16 + rg * 8) << 2)));
                unsigned pa[4][4], pb[4][4];
                #pragma unroll
                for (int mt = 0; mt < 4; ++mt) {
                    pa[mt][0] = __float_as_uint(v[mt][0].x); pa[mt][1] = __float_as_uint(v[mt][1].x);
                    pa[mt][2] = __float_as_uint(v[mt][0].y); pa[mt][3] = __float_as_uint(v[mt][1].y);
                    pb[mt][0] = __float_as_uint(v[mt][0].z); pb[mt][1] = __float_as_uint(v[mt][1].z);
                    pb[mt][2] = __float_as_uint(v[mt][0].w); pb[mt][3] = __float_as_uint(v[mt][1].w);
                }
                const int boff = t * 16 + q * 4;
                #pragma unroll
                for (int j = 0; j < 6; ++j) {
                    float4 b = *(const float4*)&Wsm[(j * 8 + gid) * WST + boff];
                    #pragma unroll
                    for (int mt = 0; mt < 4; ++mt) {
                        mma_tf32(acc[j][mt], pa[mt], b.x, b.y);
                        mma_tf32(acc[j][mt], pb[mt], b.z, b.w);
                    }
                }
            }
        } else if (p >= 1) {
            // ---------- grp1: side 2 (A = h1[p-2]), K half, 4 m-tiles ----------
            #pragma unroll 2
            for (int tt = 0; tt < 16; ++tt) {
                const int t = ks * 16 + tt;
                const float* ab = A1 + ((q * 32 + t) << 10);
                float4 v[4][2];
                #pragma unroll
                for (int mt = 0; mt < 4; ++mt)
                    #pragma unroll
                    for (int rg = 0; rg < 2; ++rg)
                        v[mt][rg] = __ldcg((const float4*)(ab + ((r0 + mt * 16 + rg * 8) << 2)));
                unsigned pa[4][4], pb[4][4];
                #pragma unroll
                for (int mt = 0; mt < 4; ++mt) {
                    pa[mt][0] = __float_as_uint(v[mt][0].x); pa[mt][1] = __float_as_uint(v[mt][1].x);
                    pa[mt][2] = __float_as_uint(v[mt][0].y); pa[mt][3] = __float_as_uint(v[mt][1].y);
                    pb[mt][0] = __float_as_uint(v[mt][0].z); pb[mt][1] = __float_as_uint(v[mt][1].z);
                    pb[mt][2] = __float_as_uint(v[mt][0].w); pb[mt][3] = __float_as_uint(v[mt][1].w);
                }
                const int boff = t * 16 + q * 4;
                #pragma unroll
                for (int j = 0; j < 3; ++j) {
                    float4 b = *(const float4*)&Wsm[((j + 6) * 8 + gid) * WST + boff];
                    #pragma unroll
                    for (int mt = 0; mt < 4; ++mt) {
                        mma_tf32(acc[j][mt], pa[mt], b.x, b.y);
                        mma_tf32(acc[j][mt], pb[mt], b.z, b.w);
                    }
                }
            }
        }

        // publish partials
        if (!g1) {
            if (ks == 1) {
                #pragma unroll
                for (int j = 0; j < 6; ++j)
                    #pragma unroll
                    for (int mt = 0; mt < 4; ++mt)
                        #pragma unroll
                        for (int hh = 0; hh < 2; ++hh) {
                            int rl = mg * 64 + mt * 16 + hh * 8 + gid;
                            *(float2*)&xch0[rl * XST0 + j * 8 + q * 2] =
                                make_float2(acc[j][mt][hh * 2], acc[j][mt][hh * 2 + 1]);
                        }
            } else {
                #pragma unroll
                for (int j = 3; j < 6; ++j)
                    #pragma unroll
                    for (int mt = 0; mt < 4; ++mt)
                        #pragma unroll
                        for (int hh = 0; hh < 2; ++hh) {
                            int rl = mg * 64 + mt * 16 + hh * 8 + gid;
                            *(float2*)&xch1[rl * XST2 + (j - 3) * 8 + q * 2] =
                                make_float2(acc[j][mt][hh * 2], acc[j][mt][hh * 2 + 1]);
                        }
            }
        } else if (ks == 1 && p >= 1) {
            #pragma unroll
            for (int j = 0; j < 3; ++j)
                #pragma unroll
                for (int mt = 0; mt < 4; ++mt)
                    #pragma unroll
                    for (int hh = 0; hh < 2; ++hh) {
                        int rl = mg * 64 + mt * 16 + hh * 8 + gid;
                        *(float2*)&xch2[rl * XST2 + j * 8 + q * 2] =
                            make_float2(acc[j][mt][hh * 2], acc[j][mt][hh * 2 + 1]);
                    }
        }

        __syncthreads();   // single convergent rendezvous

        if (!g1 && ks == 0) {
            // ---------- layer0 cells ----------
            #pragma unroll
            for (int mt = 0; mt < 4; ++mt)
            #pragma unroll
            for (int hh = 0; hh < 2; ++hh) {
                const int rl = mg * 64 + mt * 16 + hh * 8 + gid;
                const int rg = ms * 128 + rl;
                const float* xrow = xsm + rl * INDIM;
                float2 pr = *(const float2*)&xch0[rl * XST0 + 0 * 8 + q * 2];
                float2 pz = *(const float2*)&xch0[rl * XST0 + 1 * 8 + q * 2];
                float2 pn = *(const float2*)&xch0[rl * XST0 + 2 * 8 + q * 2];
                float res[2];
                #pragma unroll
                for (int e = 0; e < 2; ++e) {
                    const int uu = q + 4 * e;         // units {q, q+4}
                    const int cr = hh * 2 + e;
                    float hr = acc[0][mt][cr] + (e ? pr.y : pr.x);
                    float hz = acc[1][mt][cr] + (e ? pz.y : pz.x);
                    float hn = acc[2][mt][cr] + (e ? pn.y : pn.x);
                    float xr = b0i[uu], xz = b0i[8 + uu], xn = b0i[16 + uu];
                    #pragma unroll
                    for (int k = 0; k < INDIM; ++k) {
                        float xv = xrow[k];
                        xr += xv * wih[uu * INDIM + k];
                        xz += xv * wih[(8 + uu) * INDIM + k];
                        xn += xv * wih[(16 + uu) * INDIM + k];
                    }
                    float r = sig_(xr + hr + b0h[uu]);
                    float z = sig_(xz + hz + b0h[8 + uu]);
                    float n = tanh_(xn + r * (hn + b0h[16 + uu]));
                    res[e] = to_tf32((1.f - z) * n + z * hc[mt][hh][e]);
                    hc[mt][hh][e] = res[e];
                }
                __stcg((float2*)(H0n + hoff(U + q, rg)), make_float2(res[0], res[1]));
            }
        } else if (g1 && ks == 0 && p >= 1) {
            // ---------- layer1 cells: gi = xch0[3..5]+xch1; gh = acc[0..2]+xch2 ----------
            #pragma unroll
            for (int mt = 0; mt < 4; ++mt)
            #pragma unroll
            for (int hh = 0; hh < 2; ++hh) {
                const int rl = mg * 64 + mt * 16 + hh * 8 + gid;
                const int rg = ms * 128 + rl;
                float2 ar = *(const float2*)&xch0[rl * XST0 + 3 * 8 + q * 2];
                float2 az = *(const float2*)&xch0[rl * XST0 + 4 * 8 + q * 2];
                float2 an = *(const float2*)&xch0[rl * XST0 + 5 * 8 + q * 2];
                float2 br = *(const float2*)&xch1[rl * XST2 + 0 * 8 + q * 2];
                float2 bz = *(const float2*)&xch1[rl * XST2 + 1 * 8 + q * 2];
                float2 bn = *(const float2*)&xch1[rl * XST2 + 2 * 8 + q * 2];
                float2 cr2 = *(const float2*)&xch2[rl * XST2 + 0 * 8 + q * 2];
                float2 cz2 = *(const float2*)&xch2[rl * XST2 + 1 * 8 + q * 2];
                float2 cn2 = *(const float2*)&xch2[rl * XST2 + 2 * 8 + q * 2];
                float res[2];
                #pragma unroll
                for (int e = 0; e < 2; ++e) {
                    const int uu = q + 4 * e;
                    const int cr = hh * 2 + e;
                    float ir  = (e ? ar.y : ar.x) + (e ? br.y : br.x);
                    float iz  = (e ? az.y : az.x) + (e ? bz.y : bz.x);
                    float in_ = (e ? an.y : an.x) + (e ? bn.y : bn.x);
                    float hr  = acc[0][mt][cr] + (e ? cr2.y : cr2.x);
                    float hz  = acc[1][mt][cr] + (e ? cz2.y : cz2.x);
                    float hn  = acc[2][mt][cr] + (e ? cn2.y : cn2.x);
                    float r = sig_(ir + b1i[uu] + hr + b1h[uu]);
                    float z = sig_(iz + b1i[8 + uu] + hz + b1h[8 + uu]);
                    float n = tanh_(in_ + b1i[16 + uu] + r * (hn + b1h[16 + uu]));
                    res[e] = to_tf32((1.f - z) * n + z * hc[mt][hh][e]);
                    hc[mt][hh][e] = res[e];
                }
                __stcg((float2*)(H1n + hoff(U + q, rg)), make_float2(res[0], res[1]));
            }
        }
        grid_barrier(p);
    }

    // linear head: h1[T-1] in g_h1[1] (written at p=512)
    if (cta == 0) {
        const float* hb = g_h1[1];
        float acc2[OUTD];
        #pragma unroll
        for (int o = 0; o < OUTD; ++o) acc2[o] = bout[o];
        for (int k = 0; k < HID; ++k) {
            float hv = __ldcg(hb + hoff(k, tid));
            #pragma unroll
            for (int o = 0; o < OUTD; ++o) acc2[o] += hv * __ldg(&Wout[o * HID + k]);
        }
        #pragma unroll
        for (int o = 0; o < OUTD; ++o) out[tid * OUTD + o] = acc2[o];
    }
}

extern "C" void kernel_launch(void* const* d_in, const int* in_sizes, int n_in,
                              void* d_out, int out_size) {
    const float* x    = (const float*)d_in[0];
    const float* Wih0 = (const float*)d_in[1];
    const float* Whh0 = (const float*)d_in[2];
    const float* bih0 = (const float*)d_in[3];
    const float* bhh0 = (const float*)d_in[4];
    const float* Wih1 = (const float*)d_in[5];
    const float* Whh1 = (const float*)d_in[6];
    const float* bih1 = (const float*)d_in[7];
    const float* bhh1 = (const float*)d_in[8];
    const float* Wout = (const float*)d_in[9];
    const float* bout = (const float*)d_in[10];
    float* out = (float*)d_out;

    // 72*528 + 1024 + 192 + 96 + 128*52 + 2*128*28 = 53,152 words = 212,608 B
    const int smem_bytes = (72 * WST + 1024 + 192 + 96 + 128 * XST0 + 2 * 128 * XST2)
                           * sizeof(float);
    static int configured = 0;
    if (!configured) {
        cudaFuncSetAttribute(gru_persistent, cudaFuncAttributeMaxDynamicSharedMemorySize,
                             smem_bytes);
        configured = 1;
    }

    reset_kernel<<<128, 256>>>();
    gru_persistent<<<NCTA, THREADS, smem_bytes>>>(
        x, Wih0, Whh0, bih0, bhh0, Wih1, Whh1, bih1, bhh1, Wout, bout, out);
}

// round 11
// speedup vs baseline: 1.2672x; 1.2672x over previous
#include <cuda_runtime.h>

#define T_STEPS 512
#define BATCH   256
#define INDIM   8
#define HID     512
#define OUTD    5
#define NCTA    128
#define THREADS 384
#define WST     528            // weight row stride (words); conflict-free LDS.128
#define XST     52             // exchange row stride (words); conflict-free
#define NPHASE  (T_STEPS + 1)

__device__ float    g_h0[2][BATCH * HID];
__device__ float    g_h1[2][BATCH * HID];
__device__ unsigned g_bar[NPHASE];

// hidden element (k,row) at ((k&3)*32 + (k>>4))*1024 + row*4 + ((k>>2)&3)
__device__ __forceinline__ int hoff(int k, int row) {
    return (((k & 3) * 32 + (k >> 4)) << 10) + (row << 2) + ((k >> 2) & 3);
}
// weight in-16-block K permutation: pos = (k&3)*4 + ((k>>2)&3)
__device__ __forceinline__ int wp16(int k) {
    return (k & ~15) + ((k & 3) << 2) + ((k >> 2) & 3);
}
__device__ __forceinline__ float to_tf32(float x) {
    float r; asm("cvt.rna.tf32.f32 %0, %1;" : "=f"(r) : "f"(x)); return r;
}
__device__ __forceinline__ float sig_(float x) { return 1.f / (1.f + __expf(-x)); }
__device__ __forceinline__ float tanh_(float x) {
    float e = __expf(2.f * x); return 1.f - 2.f / (e + 1.f);
}
__device__ __forceinline__ void mma_tf32(float* c, const unsigned* a, float bx, float by) {
    asm volatile(
        "mma.sync.aligned.m16n8k8.row.col.f32.tf32.tf32.f32 "
        "{%0,%1,%2,%3}, {%4,%5,%6,%7}, {%8,%9}, {%0,%1,%2,%3};\n"
        : "+f"(c[0]), "+f"(c[1]), "+f"(c[2]), "+f"(c[3])
        : "r"(a[0]), "r"(a[1]), "r"(a[2]), "r"(a[3]),
          "r"(__float_as_uint(bx)), "r"(__float_as_uint(by)));
}

__device__ __forceinline__ void grid_barrier(int p) {
    __syncthreads();
    if (threadIdx.x == 0) {
        unsigned* c = &g_bar[p];
        asm volatile("red.release.gpu.global.add.u32 [%0], %1;" :: "l"(c), "r"(1u) : "memory");
        unsigned v;
        do {
            asm volatile("ld.acquire.gpu.global.u32 %0, [%1];" : "=r"(v) : "l"(c) : "memory");
        } while (v < NCTA);
    }
    __syncthreads();
}

__global__ void reset_kernel() {
    int tid = blockIdx.x * blockDim.x + threadIdx.x;
    int stride = gridDim.x * blockDim.x;
    for (int i = tid; i < BATCH * HID; i += stride) { g_h0[1][i] = 0.f; g_h1[1][i] = 0.f; }
    if (tid < NPHASE) g_bar[tid] = 0u;
}

extern __shared__ float smem[];

// 128 CTAs: ms = cta&1 (128-row half), U = (cta>>1)*8 (8 hidden units).
// 12 warps (R7 skeleton):
//   grp0 (w0-7)  = mg(4: 32 rows) x ks(2): sides 0+1 (tiles 0..5, A=h0[p-1]), K half
//   grp1 (w8-11) = mg(4: 32 rows): side 2 (tiles 6..8, A=h1[p-2]), full K
// Tile column c maps to unit (c>>1)+((c&1)<<2): each thread owns units {q, q+4},
// adjacent words in hoff layout -> STG.64 stores; h-prev carried in registers.
__global__ void __launch_bounds__(THREADS, 1) gru_persistent(
    const float* __restrict__ x,
    const float* __restrict__ Wih0, const float* __restrict__ Whh0,
    const float* __restrict__ bih0, const float* __restrict__ bhh0,
    const float* __restrict__ Wih1, const float* __restrict__ Whh1,
    const float* __restrict__ bih1, const float* __restrict__ bhh1,
    const float* __restrict__ Wout, const float* __restrict__ bout,
    float* __restrict__ out)
{
    float* Wsm = smem;                       // 72 x WST
    float* xsm = smem + 72 * WST;            // 128 x 8
    float* wih = xsm + 1024;                 // 24 x 8
    float* b0i = wih + 192;  float* b0h = b0i + 24;
    float* b1i = b0h + 24;   float* b1h = b1i + 24;
    float* xch0 = b1h + 24;                  // 128 x XST (grp0-ks1: tiles 0..5)
    float* xch1 = xch0 + 128 * XST;          // 128 x XST (grp0-ks0: tiles 3..5)

    const int tid  = threadIdx.x;
    const int cta  = blockIdx.x;
    const int lane = tid & 31;
    const int warp = tid >> 5;
    const int gid  = lane >> 2;
    const int q    = lane & 3;
    const bool g1  = (warp >= 8);
    const int mg   = g1 ? (warp - 8) : (warp & 3);
    const int ks   = g1 ? 0 : (warp >> 2);
    const int ms   = cta & 1;
    const int U    = (cta >> 1) * 8;

    // ---- stage weights once (column->unit remap for STG.64 epilogue) ----
    for (int i = tid; i < 72 * HID; i += THREADS) {
        int j = i >> 9, k = i & (HID - 1);
        int tile = j >> 3, c = j & 7;
        int side = tile / 3, gate = tile % 3;
        int u = (c >> 1) + ((c & 1) << 2);
        const float* W = (side == 0) ? Whh0 : (side == 1) ? Wih1 : Whh1;
        Wsm[j * WST + wp16(k)] = to_tf32(W[(gate * HID + U + u) * HID + k]);
    }
    for (int i = tid; i < 24 * INDIM; i += THREADS) {
        int j = i >> 3, kk = i & 7;
        wih[i] = Wih0[((j >> 3) * HID + U + (j & 7)) * INDIM + kk];
    }
    if (tid < 24) {
        int g3 = tid >> 3, u = tid & 7;
        b0i[tid] = bih0[g3 * HID + U + u]; b0h[tid] = bhh0[g3 * HID + U + u];
        b1i[tid] = bih1[g3 * HID + U + u]; b1h[tid] = bhh1[g3 * HID + U + u];
    }
    __syncthreads();

    // carried h-prev (already tf32-rounded), per epilogue thread: [mt][hh][e]
    float hc[2][2][2];
    #pragma unroll
    for (int mt = 0; mt < 2; ++mt)
        #pragma unroll
        for (int hh = 0; hh < 2; ++hh) { hc[mt][hh][0] = 0.f; hc[mt][hh][1] = 0.f; }

    for (int p = 0; p < NPHASE; ++p) {
        const float* A0 = g_h0[(p + 1) & 1];     // h0[p-1]
        const float* A1 = g_h1[p & 1];           // h1[p-2]
        float* H0n = g_h0[p & 1];                // h0[p]
        float* H1n = g_h1[(p + 1) & 1];          // h1[p-1]

        if (tid < 256) {
            int pp = (p < T_STEPS) ? p : (T_STEPS - 1);
            ((float4*)xsm)[tid] =
                ((const float4*)(x + ((size_t)pp * BATCH + ms * 128) * INDIM))[tid];
        }

        const int r0 = ms * 128 + mg * 32 + gid;
        const float* Ab = g1 ? A1 : A0;

        // unified accumulators: grp0 uses [0..5], grp1 uses [0..2]
        float acc[6][2][4];
        #pragma unroll
        for (int j = 0; j < 6; ++j)
            #pragma unroll
            for (int mt = 0; mt < 2; ++mt)
                #pragma unroll
                for (int e = 0; e < 4; ++e) acc[j][mt][e] = 0.f;

        if (!g1) {
            // ---------- grp0: sides 0+1 (A = h0[p-1]), K half ----------
            #pragma unroll 2
            for (int tt = 0; tt < 16; ++tt) {
                const int t = ks * 16 + tt;
                const float* ab = Ab + ((q * 32 + t) << 10);
                float4 v00 = __ldcg((const float4*)(ab + (r0 << 2)));
                float4 v01 = __ldcg((const float4*)(ab + ((r0 + 8) << 2)));
                float4 v10 = __ldcg((const float4*)(ab + ((r0 + 16) << 2)));
                float4 v11 = __ldcg((const float4*)(ab + ((r0 + 24) << 2)));
                unsigned p0[2][4] = {
                    {__float_as_uint(v00.x), __float_as_uint(v01.x),
                     __float_as_uint(v00.y), __float_as_uint(v01.y)},
                    {__float_as_uint(v10.x), __float_as_uint(v11.x),
                     __float_as_uint(v10.y), __float_as_uint(v11.y)}};
                unsigned p1[2][4] = {
                    {__float_as_uint(v00.z), __float_as_uint(v01.z),
                     __float_as_uint(v00.w), __float_as_uint(v01.w)},
                    {__float_as_uint(v10.z), __float_as_uint(v11.z),
                     __float_as_uint(v10.w), __float_as_uint(v11.w)}};
                const int boff = t * 16 + q * 4;
                #pragma unroll
                for (int j = 0; j < 6; ++j) {
                    float4 b = *(const float4*)&Wsm[(j * 8 + gid) * WST + boff];
                    mma_tf32(acc[j][0], p0[0], b.x, b.y);
                    mma_tf32(acc[j][0], p1[0], b.z, b.w);
                    mma_tf32(acc[j][1], p0[1], b.x, b.y);
                    mma_tf32(acc[j][1], p1[1], b.z, b.w);
                }
            }
            // publish partials
            if (ks == 1) {
                #pragma unroll
                for (int j = 0; j < 6; ++j)
                    #pragma unroll
                    for (int mt = 0; mt < 2; ++mt)
                        #pragma unroll
                        for (int hh = 0; hh < 2; ++hh) {
                            int rl = mg * 32 + mt * 16 + hh * 8 + gid;
                            *(float2*)&xch0[rl * XST + j * 8 + q * 2] =
                                make_float2(acc[j][mt][hh * 2], acc[j][mt][hh * 2 + 1]);
                        }
            } else {
                #pragma unroll
                for (int j = 3; j < 6; ++j)
                    #pragma unroll
                    for (int mt = 0; mt < 2; ++mt)
                        #pragma unroll
                        for (int hh = 0; hh < 2; ++hh) {
                            int rl = mg * 32 + mt * 16 + hh * 8 + gid;
                            *(float2*)&xch1[rl * XST + (j - 3) * 8 + q * 2] =
                                make_float2(acc[j][mt][hh * 2], acc[j][mt][hh * 2 + 1]);
                        }
            }
        } else {
            // ---------- grp1: side 2 (A = h1[p-2]), full K ----------
            #pragma unroll 2
            for (int t = 0; t < 32; ++t) {
                const float* ab = Ab + ((q * 32 + t) << 10);
                float4 v00 = __ldcg((const float4*)(ab + (r0 << 2)));
                float4 v01 = __ldcg((const float4*)(ab + ((r0 + 8) << 2)));
                float4 v10 = __ldcg((const float4*)(ab + ((r0 + 16) << 2)));
                float4 v11 = __ldcg((const float4*)(ab + ((r0 + 24) << 2)));
                unsigned p0[2][4] = {
                    {__float_as_uint(v00.x), __float_as_uint(v01.x),
                     __float_as_uint(v00.y), __float_as_uint(v01.y)},
                    {__float_as_uint(v10.x), __float_as_uint(v11.x),
                     __float_as_uint(v10.y), __float_as_uint(v11.y)}};
                unsigned p1[2][4] = {
                    {__float_as_uint(v00.z), __float_as_uint(v01.z),
                     __float_as_uint(v00.w), __float_as_uint(v01.w)},
                    {__float_as_uint(v10.z), __float_as_uint(v11.z),
                     __float_as_uint(v10.w), __float_as_uint(v11.w)}};
                const int boff = t * 16 + q * 4;
                #pragma unroll
                for (int j = 0; j < 3; ++j) {
                    float4 b = *(const float4*)&Wsm[((j + 6) * 8 + gid) * WST + boff];
                    mma_tf32(acc[j][0], p0[0], b.x, b.y);
                    mma_tf32(acc[j][0], p1[0], b.z, b.w);
                    mma_tf32(acc[j][1], p0[1], b.x, b.y);
                    mma_tf32(acc[j][1], p1[1], b.z, b.w);
                }
            }
        }

        __syncthreads();   // single convergent rendezvous: partials visible

        if (!g1 && ks == 0) {
            // ---------- layer0 cells: gh = acc[0..2] + xch0[0..2] ----------
            #pragma unroll
            for (int mt = 0; mt < 2; ++mt)
            #pragma unroll
            for (int hh = 0; hh < 2; ++hh) {
                const int rl = mg * 32 + mt * 16 + hh * 8 + gid;
                const int rg = ms * 128 + rl;
                const float* xrow = xsm + rl * INDIM;
                float2 pr = *(const float2*)&xch0[rl * XST + 0 * 8 + q * 2];
                float2 pz = *(const float2*)&xch0[rl * XST + 1 * 8 + q * 2];
                float2 pn = *(const float2*)&xch0[rl * XST + 2 * 8 + q * 2];
                float res[2];
                #pragma unroll
                for (int e = 0; e < 2; ++e) {
                    const int uu = q + 4 * e;        // units {q, q+4}
                    const int cr = hh * 2 + e;
                    float hr = acc[0][mt][cr] + (e ? pr.y : pr.x);
                    float hz = acc[1][mt][cr] + (e ? pz.y : pz.x);
                    float hn = acc[2][mt][cr] + (e ? pn.y : pn.x);
                    float xr = b0i[uu], xz = b0i[8 + uu], xn = b0i[16 + uu];
                    #pragma unroll
                    for (int k = 0; k < INDIM; ++k) {
                        float xv = xrow[k];
                        xr += xv * wih[uu * INDIM + k];
                        xz += xv * wih[(8 + uu) * INDIM + k];
                        xn += xv * wih[(16 + uu) * INDIM + k];
                    }
                    float r = sig_(xr + hr + b0h[uu]);
                    float z = sig_(xz + hz + b0h[8 + uu]);
                    float n = tanh_(xn + r * (hn + b0h[16 + uu]));
                    res[e] = to_tf32((1.f - z) * n + z * hc[mt][hh][e]);
                    hc[mt][hh][e] = res[e];
                }
                __stcg((float2*)(H0n + hoff(U + q, rg)), make_float2(res[0], res[1]));
            }
        } else if (g1 && p >= 1) {
            // ---------- layer1 cells: gi = xch0[3..5] + xch1[0..2]; gh = acc ----------
            #pragma unroll
            for (int mt = 0; mt < 2; ++mt)
            #pragma unroll
            for (int hh = 0; hh < 2; ++hh) {
                const int rl = mg * 32 + mt * 16 + hh * 8 + gid;
                const int rg = ms * 128 + rl;
                float2 ar = *(const float2*)&xch0[rl * XST + 3 * 8 + q * 2];
                float2 az = *(const float2*)&xch0[rl * XST + 4 * 8 + q * 2];
                float2 an = *(const float2*)&xch0[rl * XST + 5 * 8 + q * 2];
                float2 br = *(const float2*)&xch1[rl * XST + 0 * 8 + q * 2];
                float2 bz = *(const float2*)&xch1[rl * XST + 1 * 8 + q * 2];
                float2 bn = *(const float2*)&xch1[rl * XST + 2 * 8 + q * 2];
                float res[2];
                #pragma unroll
                for (int e = 0; e < 2; ++e) {
                    const int uu = q + 4 * e;
                    const int cr = hh * 2 + e;
                    float ir  = (e ? ar.y : ar.x) + (e ? br.y : br.x);
                    float iz  = (e ? az.y : az.x) + (e ? bz.y : bz.x);
                    float in_ = (e ? an.y : an.x) + (e ? bn.y : bn.x);
                    float r = sig_(ir + b1i[uu] + acc[0][mt][cr] + b1h[uu]);
                    float z = sig_(iz + b1i[8 + uu] + acc[1][mt][cr] + b1h[8 + uu]);
                    float n = tanh_(in_ + b1i[16 + uu]
                                    + r * (acc[2][mt][cr] + b1h[16 + uu]));
                    res[e] = to_tf32((1.f - z) * n + z * hc[mt][hh][e]);
                    hc[mt][hh][e] = res[e];
                }
                __stcg((float2*)(H1n + hoff(U + q, rg)), make_float2(res[0], res[1]));
            }
        }
        grid_barrier(p);
    }

    // linear head: h1[T-1] in g_h1[1] (written at p=512)
    if (cta == 0 && tid < 256) {
        const float* hb = g_h1[1];
        float acc2[OUTD];
        #pragma unroll
        for (int o = 0; o < OUTD; ++o) acc2[o] = bout[o];
        for (int k = 0; k < HID; ++k) {
            float hv = __ldcg(hb + hoff(k, tid));
            #pragma unroll
            for (int o = 0; o < OUTD; ++o) acc2[o] += hv * __ldg(&Wout[o * HID + k]);
        }
        #pragma unroll
        for (int o = 0; o < OUTD; ++o) out[tid * OUTD + o] = acc2[o];
    }
}

extern "C" void kernel_launch(void* const* d_in, const int* in_sizes, int n_in,
                              void* d_out, int out_size) {
    const float* x    = (const float*)d_in[0];
    const float* Wih0 = (const float*)d_in[1];
    const float* Whh0 = (const float*)d_in[2];
    const float* bih0 = (const float*)d_in[3];
    const float* bhh0 = (const float*)d_in[4];
    const float* Wih1 = (const float*)d_in[5];
    const float* Whh1 = (const float*)d_in[6];
    const float* bih1 = (const float*)d_in[7];
    const float* bhh1 = (const float*)d_in[8];
    const float* Wout = (const float*)d_in[9];
    const float* bout = (const float*)d_in[10];
    float* out = (float*)d_out;

    // 72*528 + 1024 + 192 + 96 + 2*128*52 = 52,640 words = 210,560 B
    const int smem_bytes = (72 * WST + 1024 + 192 + 96 + 2 * 128 * XST) * sizeof(float);
    static int configured = 0;
    if (!configured) {
        cudaFuncSetAttribute(gru_persistent, cudaFuncAttributeMaxDynamicSharedMemorySize,
                             smem_bytes);
        configured = 1;
    }

    reset_kernel<<<128, 256>>>();
    gru_persistent<<<NCTA, THREADS, smem_bytes>>>(
        x, Wih0, Whh0, bih0, bhh0, Wih1, Whh1, bih1, bhh1, Wout, bout, out);
}